// round 14
// baseline (speedup 1.0000x reference)
#include <cuda_runtime.h>
#include <cuda_fp16.h>
#include <cstdint>
#include <cstddef>

#define BB 4
#define CC 32
#define DD 64
#define HH 128
#define WW 256
#define HW_ (HH*WW)          // 32768
#define BDHW_ (BB*DD*HW_)    // 8388608
#define BCHW_ (BB*CC*HW_)    // 4194304
#define NROWS (BB*HH*WW)     // 131072

// ---------------- scratch (static device globals; no allocation) ----------------
__device__ float g_conv[BDHW_];
__device__ float g_xA[BDHW_];
__device__ float g_xB[BDHW_];
__device__ __half g_vth[BDHW_];      // v fp16, [b][h][w][d]
__device__ __half g_ohth[BDHW_];     // oH fp16 (normalized), [b][h][w][d]
__device__ __half g_qth[BCHW_];      // q fp16, [b][h][w][c]
__device__ __half g_kth[BCHW_];      // k fp16, [b][h][w][c]
__device__ __half g_aHh[BB*HH*WW*HH];  // fp16 exp(scores) (H part)
__device__ __half g_aWh[BB*HH*WW*WW];  // fp16 exp(scores) (W part)
__device__ float g_rsum[NROWS];      // per-row softmax denominators
__device__ __half g_wth[9*64*64];    // fp16 conv weights [t][d][c]
__device__ float g_cs[128];          // channel sums [0:64] and sumsq [64:128]
__device__ float2 g_stats[64];       // (mean, inv)
__device__ float2 g_bnab[64];        // (sa, sb): BN as affine
__device__ float g_wf[64*64];        // BN-folded 1x1 v-conv weights
__device__ float g_bf[64];           // BN-folded bias

// ---------------- weight transform ----------------
__global__ void wtrans_kernel(const float* __restrict__ W, __half* __restrict__ wth) {
    const int i = blockIdx.x * 256 + threadIdx.x;
    if (i >= 9 * 64 * 64) return;
    const int t = i >> 12;
    const int d = (i >> 6) & 63;
    const int c = i & 63;
    wth[i] = __float2half(W[((d * 64 + c) * 9) + t]);
}

// ---------------- mma / ldmatrix helpers ----------------
__device__ __forceinline__ void mma_f16(float* c, uint32_t a0, uint32_t a1, uint32_t a2, uint32_t a3,
                                        uint32_t b0, uint32_t b1) {
    asm volatile("mma.sync.aligned.m16n8k16.row.col.f32.f16.f16.f32 "
                 "{%0,%1,%2,%3}, {%4,%5,%6,%7}, {%8,%9}, {%0,%1,%2,%3};"
                 : "+f"(c[0]), "+f"(c[1]), "+f"(c[2]), "+f"(c[3])
                 : "r"(a0), "r"(a1), "r"(a2), "r"(a3), "r"(b0), "r"(b1));
}

__device__ __forceinline__ uint32_t cvta_smem(const void* p) {
    return (uint32_t)__cvta_generic_to_shared(p);
}

__device__ __forceinline__ void ldsm_x4(uint32_t& r0, uint32_t& r1, uint32_t& r2, uint32_t& r3,
                                        uint32_t addr) {
    asm volatile("ldmatrix.sync.aligned.m8n8.x4.shared.b16 {%0,%1,%2,%3}, [%4];"
                 : "=r"(r0), "=r"(r1), "=r"(r2), "=r"(r3) : "r"(addr));
}

__device__ __forceinline__ void ldsm_x4_trans(uint32_t& r0, uint32_t& r1, uint32_t& r2, uint32_t& r3,
                                              uint32_t addr) {
    asm volatile("ldmatrix.sync.aligned.m8n8.x4.trans.shared.b16 {%0,%1,%2,%3}, [%4];"
                 : "=r"(r0), "=r"(r1), "=r"(r2), "=r"(r3) : "r"(addr));
}

// ---------------- fast exp ----------------
__device__ __forceinline__ float fexp(float x) {
    x = fmaxf(x, -80.f);
    const float y = x * 1.44269504f;
    const int e = __float2int_rn(y);
    const float f = y - (float)e;
    float p = 0.00133335581f;
    p = fmaf(p, f, 0.00961812910f);
    p = fmaf(p, f, 0.0555041086f);
    p = fmaf(p, f, 0.240226507f);
    p = fmaf(p, f, 0.693147182f);
    p = fmaf(p, f, 1.0f);
    return p * __int_as_float((e + 127) << 23);
}

// ---------------- conv3x3: fp16 mma + ldmatrix + double-buffered weights + BN-stat atomics ----------------
#define CXS_STRIDE 72
#define CXS_HALVES (4*66*72)    // 19008
#define CWS_BUF 4608            // one weight buffer [64][72]
#define CONV_SMEM ((CXS_HALVES + 2*CWS_BUF) * 2)   // 56448 bytes

__global__ __launch_bounds__(256)
void conv3x3_mma_kernel(const float* __restrict__ x, const __half* __restrict__ wth,
                        float* __restrict__ y, float* __restrict__ cs1, float* __restrict__ cs2) {
    extern __shared__ __half shc[];
    __half* xs = shc;                  // [(r*66+col)][72]
    __half* ws = shc + CXS_HALVES;     // 2 x [64][72]

    const int w0 = blockIdx.x * 64;
    const int h0 = blockIdx.y * 2;
    const int b  = blockIdx.z;
    const int tid = threadIdx.x;
    const int lane = tid & 31;
    const int warp = tid >> 5;
    const int hsel = warp >> 2;
    const int d0 = (warp & 3) * 16;
    const int g8 = lane >> 2;
    const int t2 = (lane & 3) * 2;

    for (int i = tid; i < 64 * 4 * 66; i += 256) {
        const int c = i / 264;
        const int rem = i - c * 264;
        const int r = rem / 66;
        const int col = rem - r * 66;
        const int gh = h0 + r - 1;
        const int gw = w0 + col - 1;
        float v = 0.f;
        if (gh >= 0 && gh < HH && gw >= 0 && gw < WW)
            v = x[((size_t)(b * 64 + c)) * HW_ + gh * WW + gw];
        xs[(r * 66 + col) * CXS_STRIDE + c] = __float2half(v);
    }
    // preload tap 0 weights into buffer 0
    for (int i = tid; i < 4096; i += 256)
        ws[(i >> 6) * CXS_STRIDE + (i & 63)] = wth[i];
    __syncthreads();

    float acc[8][4];
#pragma unroll
    for (int j = 0; j < 8; ++j)
#pragma unroll
        for (int k = 0; k < 4; ++k) acc[j][k] = 0.f;

    const uint32_t ws_base = cvta_smem(ws);
    const uint32_t xs_base = cvta_smem(xs);
    const uint32_t a_off = ((uint32_t)((d0 + (lane & 15)) * CXS_STRIDE + ((lane >> 4) << 3))) * 2;
    const uint32_t b_off = ((uint32_t)((((lane >> 4) << 3) + (lane & 7)) * CXS_STRIDE
                                       + (((lane >> 3) & 1) << 3))) * 2;

    for (int t = 0; t < 9; ++t) {
        // prefetch tap t+1 into alternate buffer (overlaps with compute)
        if (t < 8) {
            const __half* wp = wth + (t + 1) * 4096;
            __half* wn = ws + ((t + 1) & 1) * CWS_BUF;
            for (int i = tid; i < 4096; i += 256)
                wn[(i >> 6) * CXS_STRIDE + (i & 63)] = wp[i];
        }
        const uint32_t wcur = ws_base + (uint32_t)((t & 1) * CWS_BUF) * 2;
        const int dh = t / 3;
        const int dw = t - dh * 3;
        const int colrow = (hsel + dh) * 66 + dw;
        const uint32_t b_tap = xs_base + b_off + (uint32_t)(colrow * CXS_STRIDE) * 2;
#pragma unroll
        for (int kb = 0; kb < 64; kb += 16) {
            uint32_t a0, a1, a2, a3;
            ldsm_x4(a0, a1, a2, a3, wcur + a_off + kb * 2);
#pragma unroll
            for (int jj = 0; jj < 4; ++jj) {
                uint32_t b0, b1, c0, c1;
                ldsm_x4(b0, b1, c0, c1, b_tap + (uint32_t)(jj * 16 * CXS_STRIDE + kb) * 2);
                mma_f16(acc[2 * jj],     a0, a1, a2, a3, b0, b1);
                mma_f16(acc[2 * jj + 1], a0, a1, a2, a3, c0, c1);
            }
        }
        __syncthreads();
    }

    const int h = h0 + hsel;
    float s_lo = 0.f, q_lo = 0.f, s_hi = 0.f, q_hi = 0.f;
#pragma unroll
    for (int j = 0; j < 8; ++j) {
        const int w = w0 + j * 8 + t2;
        const size_t base = ((size_t)(b * 64 + d0 + g8)) * HW_ + (size_t)h * WW + w;
        *reinterpret_cast<float2*>(y + base) = make_float2(acc[j][0], acc[j][1]);
        *reinterpret_cast<float2*>(y + base + (size_t)8 * HW_) = make_float2(acc[j][2], acc[j][3]);
        s_lo += acc[j][0] + acc[j][1];
        q_lo += acc[j][0] * acc[j][0] + acc[j][1] * acc[j][1];
        s_hi += acc[j][2] + acc[j][3];
        q_hi += acc[j][2] * acc[j][2] + acc[j][3] * acc[j][3];
    }
    s_lo += __shfl_xor_sync(0xffffffffu, s_lo, 1); s_lo += __shfl_xor_sync(0xffffffffu, s_lo, 2);
    q_lo += __shfl_xor_sync(0xffffffffu, q_lo, 1); q_lo += __shfl_xor_sync(0xffffffffu, q_lo, 2);
    s_hi += __shfl_xor_sync(0xffffffffu, s_hi, 1); s_hi += __shfl_xor_sync(0xffffffffu, s_hi, 2);
    q_hi += __shfl_xor_sync(0xffffffffu, q_hi, 1); q_hi += __shfl_xor_sync(0xffffffffu, q_hi, 2);
    if ((lane & 3) == 0) {
        atomicAdd(cs1 + d0 + g8, s_lo);
        atomicAdd(cs2 + d0 + g8, q_lo);
        atomicAdd(cs1 + d0 + g8 + 8, s_hi);
        atomicAdd(cs2 + d0 + g8 + 8, q_hi);
    }
}

// ---------------- BN finalize: stats + affine ----------------
__global__ void bn_finalize_kernel(const float* __restrict__ cs1, const float* __restrict__ cs2,
                                   const float* __restrict__ gam, const float* __restrict__ bet,
                                   float2* __restrict__ stats, float2* __restrict__ bnab) {
    const int c = threadIdx.x;
    const float inv_n = 1.f / 131072.f;
    const float mean = cs1[c] * inv_n;
    const float var  = cs2[c] * inv_n - mean * mean;
    const float inv  = rsqrtf(var + 1e-5f);
    stats[c] = make_float2(mean, inv);
    const float sa = inv * gam[c];
    bnab[c] = make_float2(sa, bet[c] - mean * sa);
}

// ---------------- fold BN into 1x1 v-conv weights ----------------
__global__ void wfold_kernel(const float* __restrict__ Wv, const float* __restrict__ bv,
                             const float2* __restrict__ bnab,
                             float* __restrict__ wf, float* __restrict__ bf) {
    const int dout = threadIdx.x;   // 64 threads
    float bb = bv[dout];
    for (int c = 0; c < 64; ++c) {
        const float w = Wv[dout * 64 + c];
        const float2 ab = bnab[c];
        wf[dout * 64 + c] = w * ab.x;
        bb += w * ab.y;
    }
    bf[dout] = bb;
}

// ---------------- bn_apply (stage D only) ----------------
__global__ void bn_apply_kernel(const float* __restrict__ x, const float2* __restrict__ stats,
                                const float* __restrict__ gam, const float* __restrict__ bet,
                                float* __restrict__ y) {
    const int idx = blockIdx.x * 256 + threadIdx.x;
    const int e = idx * 4;
    const int c = (e / HW_) & 63;
    const float2 st = stats[c];
    const float g = gam[c], be = bet[c];
    float4 v = reinterpret_cast<const float4*>(x)[idx];
    v.x = (v.x - st.x) * st.y * g + be;
    v.y = (v.y - st.x) * st.y * g + be;
    v.z = (v.z - st.x) * st.y * g + be;
    v.w = (v.w - st.x) * st.y * g + be;
    reinterpret_cast<float4*>(y)[idx] = v;
}

// ---------------- 1x1 convs ----------------
__global__ void conv1x1_c32_kernel(const float* __restrict__ x, const float* __restrict__ wgt,
                                   const float* __restrict__ bias, __half* __restrict__ yt) {
    __shared__ float sw[32][33];
    __shared__ float sb[32];
    const int tid = threadIdx.x;
    for (int i = tid; i < 1024; i += 256) sw[i >> 5][i & 31] = wgt[i];
    if (tid < 32) sb[tid] = bias[tid];
    __syncthreads();
    const int pos = blockIdx.x * 256 + tid;
    const int b = pos >> 15, i = pos & 32767;
    float xin[32];
#pragma unroll
    for (int ci = 0; ci < 32; ++ci) xin[ci] = x[((size_t)(b * 32 + ci)) * HW_ + i];
    __half* out = yt + (size_t)pos * 32;
#pragma unroll
    for (int co = 0; co < 32; co += 4) {
        float4 a = make_float4(sb[co], sb[co + 1], sb[co + 2], sb[co + 3]);
#pragma unroll
        for (int ci = 0; ci < 32; ++ci) {
            const float xv = xin[ci];
            a.x += sw[co][ci] * xv; a.y += sw[co + 1][ci] * xv;
            a.z += sw[co + 2][ci] * xv; a.w += sw[co + 3][ci] * xv;
        }
        *reinterpret_cast<__half2*>(out + co)     = __floats2half2_rn(a.x, a.y);
        *reinterpret_cast<__half2*>(out + co + 2) = __floats2half2_rn(a.z, a.w);
    }
}

__global__ void conv1x1_d64_kernel(const float* __restrict__ x, const float* __restrict__ wgt,
                                   const float* __restrict__ bias, __half* __restrict__ vth) {
    __shared__ float sw[64][65];
    __shared__ float sb[64];
    const int tid = threadIdx.x;
    for (int i = tid; i < 4096; i += 256) sw[i >> 6][i & 63] = wgt[i];
    if (tid < 64) sb[tid] = bias[tid];
    __syncthreads();
    const int pos = blockIdx.x * 256 + tid;
    const int b = pos >> 15, i = pos & 32767;
    float xin[64];
#pragma unroll
    for (int ci = 0; ci < 64; ++ci) xin[ci] = x[((size_t)(b * 64 + ci)) * HW_ + i];
    __half* out = vth + (size_t)pos * 64;
#pragma unroll
    for (int co = 0; co < 64; co += 4) {
        float4 a = make_float4(sb[co], sb[co + 1], sb[co + 2], sb[co + 3]);
#pragma unroll
        for (int ci = 0; ci < 64; ++ci) {
            const float xv = xin[ci];
            a.x += sw[co][ci] * xv; a.y += sw[co + 1][ci] * xv;
            a.z += sw[co + 2][ci] * xv; a.w += sw[co + 3][ci] * xv;
        }
        *reinterpret_cast<__half2*>(out + co)     = __floats2half2_rn(a.x, a.y);
        *reinterpret_cast<__half2*>(out + co + 2) = __floats2half2_rn(a.z, a.w);
    }
}

// ---------------- eH via HMMA + fused exp + row-sum ----------------
#define ES_STRIDE 40

__global__ __launch_bounds__(256)
void eH_kernel(const __half* __restrict__ qth, const __half* __restrict__ kth,
               __half* __restrict__ aHh, float* __restrict__ rsum) {
    __shared__ __half Qs[128 * ES_STRIDE];
    __shared__ __half Ks[128 * ES_STRIDE];
    const int w = blockIdx.x, b = blockIdx.y;
    const int tid = threadIdx.x;
    const int lane = tid & 31, warp = tid >> 5;
    const int g8 = lane >> 2, t2 = (lane & 3) * 2;

    for (int i = tid; i < 512; i += 256) {
        const int row = i >> 2, seg = (i & 3) * 8;
        const size_t gidx = (((size_t)b * HH + row) * WW + w) * 32 + seg;
        *reinterpret_cast<uint4*>(Qs + row * ES_STRIDE + seg) =
            *reinterpret_cast<const uint4*>(qth + gidx);
        *reinterpret_cast<uint4*>(Ks + row * ES_STRIDE + seg) =
            *reinterpret_cast<const uint4*>(kth + gidx);
    }
    __syncthreads();

    float acc[16][4];
#pragma unroll
    for (int ni = 0; ni < 16; ++ni)
#pragma unroll
        for (int k = 0; k < 4; ++k) acc[ni][k] = 0.f;

    const int h0 = warp * 16;
#pragma unroll
    for (int kb = 0; kb < 32; kb += 16) {
        const __half* ap = Qs + (h0 + g8) * ES_STRIDE + kb + t2;
        const uint32_t a0 = *reinterpret_cast<const uint32_t*>(ap);
        const uint32_t a1 = *reinterpret_cast<const uint32_t*>(ap + 8 * ES_STRIDE);
        const uint32_t a2 = *reinterpret_cast<const uint32_t*>(ap + 8);
        const uint32_t a3 = *reinterpret_cast<const uint32_t*>(ap + 8 * ES_STRIDE + 8);
#pragma unroll
        for (int ni = 0; ni < 16; ++ni) {
            const __half* bp = Ks + (ni * 8 + g8) * ES_STRIDE + kb + t2;
            const uint32_t b0 = *reinterpret_cast<const uint32_t*>(bp);
            const uint32_t b1 = *reinterpret_cast<const uint32_t*>(bp + 8);
            mma_f16(acc[ni], a0, a1, a2, a3, b0, b1);
        }
    }

    const int h1 = h0 + g8, h2 = h1 + 8;
    float s1 = 0.f, s2 = 0.f;
#pragma unroll
    for (int ni = 0; ni < 16; ++ni) {
        const int g = ni * 8 + t2;
        const float e0 = (h1 == g)     ? 0.f : fexp(acc[ni][0]);
        const float e1 = (h1 == g + 1) ? 0.f : fexp(acc[ni][1]);
        const float e2 = (h2 == g)     ? 0.f : fexp(acc[ni][2]);
        const float e3 = (h2 == g + 1) ? 0.f : fexp(acc[ni][3]);
        s1 += e0 + e1;
        s2 += e2 + e3;
        *reinterpret_cast<__half2*>(aHh + (((size_t)b * HH + h1) * WW + w) * 128 + g) =
            __floats2half2_rn(e0, e1);
        *reinterpret_cast<__half2*>(aHh + (((size_t)b * HH + h2) * WW + w) * 128 + g) =
            __floats2half2_rn(e2, e3);
    }
    s1 += __shfl_xor_sync(0xffffffffu, s1, 1);
    s1 += __shfl_xor_sync(0xffffffffu, s1, 2);
    s2 += __shfl_xor_sync(0xffffffffu, s2, 1);
    s2 += __shfl_xor_sync(0xffffffffu, s2, 2);
    if ((lane & 3) == 0) {
        atomicAdd(rsum + ((size_t)b * HH + h1) * WW + w, s1);
        atomicAdd(rsum + ((size_t)b * HH + h2) * WW + w, s2);
    }
}

// ---------------- eW via HMMA + fused exp + row-sum ----------------
__global__ __launch_bounds__(256)
void eW_kernel(const __half* __restrict__ qth, const __half* __restrict__ kth,
               __half* __restrict__ aWh, float* __restrict__ rsum) {
    __shared__ __half Qs[256 * ES_STRIDE];
    __shared__ __half Ks[64 * ES_STRIDE];
    const int gc = blockIdx.x * 64;
    const int h = blockIdx.y, b = blockIdx.z;
    const int tid = threadIdx.x;
    const int lane = tid & 31, warp = tid >> 5;
    const int g8 = lane >> 2, t2 = (lane & 3) * 2;

    const __half* qbase = qth + (((size_t)b * HH + h) * WW) * 32;
    for (int i = tid; i < 1024; i += 256) {
        const int row = i >> 2, seg = (i & 3) * 8;
        *reinterpret_cast<uint4*>(Qs + row * ES_STRIDE + seg) =
            *reinterpret_cast<const uint4*>(qbase + row * 32 + seg);
    }
    const __half* kbase = kth + (((size_t)b * HH + h) * WW + gc) * 32;
    {
        const int i = tid;
        const int row = i >> 2, seg = (i & 3) * 8;
        *reinterpret_cast<uint4*>(Ks + row * ES_STRIDE + seg) =
            *reinterpret_cast<const uint4*>(kbase + row * 32 + seg);
    }
    __syncthreads();

    float acc[2][8][4];
#pragma unroll
    for (int mi = 0; mi < 2; ++mi)
#pragma unroll
        for (int ni = 0; ni < 8; ++ni)
#pragma unroll
            for (int k = 0; k < 4; ++k) acc[mi][ni][k] = 0.f;

    const int w0 = warp * 32;
#pragma unroll
    for (int kb = 0; kb < 32; kb += 16) {
        uint32_t a[2][4];
#pragma unroll
        for (int mi = 0; mi < 2; ++mi) {
            const __half* ap = Qs + (w0 + mi * 16 + g8) * ES_STRIDE + kb + t2;
            a[mi][0] = *reinterpret_cast<const uint32_t*>(ap);
            a[mi][1] = *reinterpret_cast<const uint32_t*>(ap + 8 * ES_STRIDE);
            a[mi][2] = *reinterpret_cast<const uint32_t*>(ap + 8);
            a[mi][3] = *reinterpret_cast<const uint32_t*>(ap + 8 * ES_STRIDE + 8);
        }
#pragma unroll
        for (int ni = 0; ni < 8; ++ni) {
            const __half* bp = Ks + (ni * 8 + g8) * ES_STRIDE + kb + t2;
            const uint32_t b0 = *reinterpret_cast<const uint32_t*>(bp);
            const uint32_t b1 = *reinterpret_cast<const uint32_t*>(bp + 8);
            mma_f16(acc[0][ni], a[0][0], a[0][1], a[0][2], a[0][3], b0, b1);
            mma_f16(acc[1][ni], a[1][0], a[1][1], a[1][2], a[1][3], b0, b1);
        }
    }

#pragma unroll
    for (int mi = 0; mi < 2; ++mi) {
        const int w1 = w0 + mi * 16 + g8, w2 = w1 + 8;
        float s1 = 0.f, s2 = 0.f;
#pragma unroll
        for (int ni = 0; ni < 8; ++ni) {
            const int g = gc + ni * 8 + t2;
            const float e0 = fexp(acc[mi][ni][0]);
            const float e1 = fexp(acc[mi][ni][1]);
            const float e2 = fexp(acc[mi][ni][2]);
            const float e3 = fexp(acc[mi][ni][3]);
            s1 += e0 + e1;
            s2 += e2 + e3;
            *reinterpret_cast<__half2*>(aWh + (((size_t)b * HH + h) * WW + w1) * 256 + g) =
                __floats2half2_rn(e0, e1);
            *reinterpret_cast<__half2*>(aWh + (((size_t)b * HH + h) * WW + w2) * 256 + g) =
                __floats2half2_rn(e2, e3);
        }
        s1 += __shfl_xor_sync(0xffffffffu, s1, 1);
        s1 += __shfl_xor_sync(0xffffffffu, s1, 2);
        s2 += __shfl_xor_sync(0xffffffffu, s2, 1);
        s2 += __shfl_xor_sync(0xffffffffu, s2, 2);
        if ((lane & 3) == 0) {
            atomicAdd(rsum + ((size_t)b * HH + h) * WW + w1, s1);
            atomicAdd(rsum + ((size_t)b * HH + h) * WW + w2, s2);
        }
    }
}

// ---------------- oH via HMMA + ldmatrix + normalization ----------------
#define ATT_SSTRIDE 136
#define VS2_STRIDE 72
#define ATT_SMEM ((128*ATT_SSTRIDE + 128*VS2_STRIDE) * 2)   // 53248 bytes

__global__ void oH_kernel(const __half* __restrict__ vth, const __half* __restrict__ aHh,
                          const float* __restrict__ rsum, __half* __restrict__ ohth) {
    extern __shared__ __half sh[];
    __half* As = sh;                       // [128 h][136] g-contiguous
    __half* Vs = sh + 128 * ATT_SSTRIDE;   // [128 g][72] d-contiguous
    const int w = blockIdx.x, b = blockIdx.y;
    const int tid = threadIdx.x;
    const int lane = tid & 31, warp = tid >> 5;
    const int g8 = lane >> 2, t2 = (lane & 3) * 2;

    for (int i = tid; i < 2048; i += 128) {
        const int row = i >> 4, ch = (i & 15) * 8;
        *reinterpret_cast<uint4*>(As + row * ATT_SSTRIDE + ch) =
            *reinterpret_cast<const uint4*>(aHh + (((size_t)b * HH + row) * WW + w) * 128 + ch);
    }
    for (int i = tid; i < 1024; i += 128) {
        const int g = i >> 3, dc = (i & 7) * 8;
        *reinterpret_cast<uint4*>(Vs + g * VS2_STRIDE + dc) =
            *reinterpret_cast<const uint4*>(vth + (((size_t)b * HH + g) * WW + w) * 64 + dc);
    }
    __syncthreads();

    float acc[2][8][4];
#pragma unroll
    for (int mi = 0; mi < 2; ++mi)
#pragma unroll
        for (int ni = 0; ni < 8; ++ni)
#pragma unroll
            for (int k = 0; k < 4; ++k) acc[mi][ni][k] = 0.f;

    const uint32_t as_base = cvta_smem(As);
    const uint32_t vs_base = cvta_smem(Vs);
    const uint32_t a_off = ((uint32_t)((lane & 15) * ATT_SSTRIDE + ((lane >> 4) << 3))) * 2;
    const uint32_t b_off = ((uint32_t)((lane & 15) * VS2_STRIDE + ((lane >> 4) << 3))) * 2;

    const int h0 = warp * 32;
#pragma unroll
    for (int kb = 0; kb < 128; kb += 16) {
        uint32_t a[2][4];
#pragma unroll
        for (int mi = 0; mi < 2; ++mi)
            ldsm_x4(a[mi][0], a[mi][1], a[mi][2], a[mi][3],
                    as_base + a_off + (uint32_t)((h0 + mi * 16) * ATT_SSTRIDE + kb) * 2);
#pragma unroll
        for (int np = 0; np < 4; ++np) {
            uint32_t b0, b1, c0, c1;
            ldsm_x4_trans(b0, b1, c0, c1,
                          vs_base + b_off + (uint32_t)(kb * VS2_STRIDE + np * 16) * 2);
            mma_f16(acc[0][2 * np],     a[0][0], a[0][1], a[0][2], a[0][3], b0, b1);
            mma_f16(acc[0][2 * np + 1], a[0][0], a[0][1], a[0][2], a[0][3], c0, c1);
            mma_f16(acc[1][2 * np],     a[1][0], a[1][1], a[1][2], a[1][3], b0, b1);
            mma_f16(acc[1][2 * np + 1], a[1][0], a[1][1], a[1][2], a[1][3], c0, c1);
        }
    }

#pragma unroll
    for (int mi = 0; mi < 2; ++mi) {
        const int h = h0 + mi * 16 + g8;
        const float inv1 = 1.f / rsum[((size_t)b * HH + h) * WW + w];
        const float inv2 = 1.f / rsum[((size_t)b * HH + h + 8) * WW + w];
#pragma unroll
        for (int ni = 0; ni < 8; ++ni) {
            const int d = ni * 8 + t2;
            *reinterpret_cast<__half2*>(ohth + (((size_t)b * HH + h) * WW + w) * 64 + d) =
                __floats2half2_rn(acc[mi][ni][0] * inv1, acc[mi][ni][1] * inv1);
            *reinterpret_cast<__half2*>(ohth + (((size_t)b * HH + h + 8) * WW + w) * 64 + d) =
                __floats2half2_rn(acc[mi][ni][2] * inv2, acc[mi][ni][3] * inv2);
        }
    }
}

// ---------------- oW via HMMA + ldmatrix + normalization + combine (+opt residual BN) ----------------
__global__ void oW_combine_kernel(const __half* __restrict__ vth, const __half* __restrict__ aWh,
                                  const __half* __restrict__ ohth, const float* __restrict__ x,
                                  const float* __restrict__ rsum, const float2* __restrict__ bnab,
                                  const int apply_bn,
                                  const float* __restrict__ gamma, float* __restrict__ xout) {
    extern __shared__ __half sh[];
    __half* As = sh;                       // [128 w][136]
    __half* Vs = sh + 128 * ATT_SSTRIDE;   // [128 g][72]
    const int wb = blockIdx.x * 128;
    const int h = blockIdx.y, b = blockIdx.z;
    const int tid = threadIdx.x;
    const int lane = tid & 31, warp = tid >> 5;
    const int g8 = lane >> 2, t2 = (lane & 3) * 2;

    float acc[2][8][4];
#pragma unroll
    for (int mi = 0; mi < 2; ++mi)
#pragma unroll
        for (int ni = 0; ni < 8; ++ni)
#pragma unroll
            for (int k = 0; k < 4; ++k) acc[mi][ni][k] = 0.f;

    const uint32_t as_base = cvta_smem(As);
    const uint32_t vs_base = cvta_smem(Vs);
    const uint32_t a_off = ((uint32_t)((lane & 15) * ATT_SSTRIDE + ((lane >> 4) << 3))) * 2;
    const uint32_t b_off = ((uint32_t)((lane & 15) * VS2_STRIDE + ((lane >> 4) << 3))) * 2;

    const int w0 = warp * 32;
    for (int gc = 0; gc < 256; gc += 128) {
        __syncthreads();
        for (int i = tid; i < 2048; i += 128) {
            const int row = i >> 4, ch = (i & 15) * 8;
            *reinterpret_cast<uint4*>(As + row * ATT_SSTRIDE + ch) =
                *reinterpret_cast<const uint4*>(
                    aWh + (((size_t)b * HH + h) * WW + wb + row) * 256 + gc + ch);
        }
        for (int i = tid; i < 1024; i += 128) {
            const int g = i >> 3, dc = (i & 7) * 8;
            *reinterpret_cast<uint4*>(Vs + g * VS2_STRIDE + dc) =
                *reinterpret_cast<const uint4*>(
                    vth + (((size_t)b * HH + h) * WW + gc + g) * 64 + dc);
        }
        __syncthreads();

#pragma unroll
        for (int kb = 0; kb < 128; kb += 16) {
            uint32_t a[2][4];
#pragma unroll
            for (int mi = 0; mi < 2; ++mi)
                ldsm_x4(a[mi][0], a[mi][1], a[mi][2], a[mi][3],
                        as_base + a_off + (uint32_t)((w0 + mi * 16) * ATT_SSTRIDE + kb) * 2);
#pragma unroll
            for (int np = 0; np < 4; ++np) {
                uint32_t b0, b1, c0, c1;
                ldsm_x4_trans(b0, b1, c0, c1,
                              vs_base + b_off + (uint32_t)(kb * VS2_STRIDE + np * 16) * 2);
                mma_f16(acc[0][2 * np],     a[0][0], a[0][1], a[0][2], a[0][3], b0, b1);
                mma_f16(acc[0][2 * np + 1], a[0][0], a[0][1], a[0][2], a[0][3], c0, c1);
                mma_f16(acc[1][2 * np],     a[1][0], a[1][1], a[1][2], a[1][3], b0, b1);
                mma_f16(acc[1][2 * np + 1], a[1][0], a[1][1], a[1][2], a[1][3], c0, c1);
            }
        }
    }

    const float gam = *gamma;
#pragma unroll
    for (int mi = 0; mi < 2; ++mi) {
#pragma unroll
        for (int half = 0; half < 2; ++half) {
            const int w = wb + w0 + mi * 16 + g8 + half * 8;
            const float inv = 1.f / rsum[((size_t)b * HH + h) * WW + w];
#pragma unroll
            for (int ni = 0; ni < 8; ++ni) {
                const int d = ni * 8 + t2;
                float sa0 = 1.f, sb0 = 0.f, sa1 = 1.f, sb1 = 0.f;
                if (apply_bn) {
                    const float2 p0 = bnab[d];
                    const float2 p1 = bnab[d + 1];
                    sa0 = p0.x; sb0 = p0.y; sa1 = p1.x; sb1 = p1.y;
                }
                const float cA = acc[mi][ni][half * 2] * inv;
                const float cB = acc[mi][ni][half * 2 + 1] * inv;
                const float2 ohf = __half22float2(*reinterpret_cast<const __half2*>(
                    ohth + (((size_t)b * HH + h) * WW + w) * 64 + d));
                const size_t x0 = ((size_t)(b * 64 + d)) * HW_ + (size_t)h * WW + w;
                const size_t x1 = ((size_t)(b * 64 + d + 1)) * HW_ + (size_t)h * WW + w;
                xout[x0] = gam * (cA + ohf.x) + (sa0 * x[x0] + sb0);
                xout[x1] = gam * (cB + ohf.y) + (sa1 * x[x1] + sb1);
            }
        }
    }
}

// ---------------- host ----------------
extern "C" void kernel_launch(void* const* d_in, const int* in_sizes, int n_in,
                              void* d_out, int out_size) {
    const float* cost  = (const float*)d_in[0];
    const float* lf0   = (const float*)d_in[1];
    const float* lf1   = (const float*)d_in[2];
    const float* Wa    = (const float*)d_in[3];
    const float* bn_ag = (const float*)d_in[4];
    const float* bn_ab = (const float*)d_in[5];
    const float* Wq    = (const float*)d_in[6];
    const float* bq    = (const float*)d_in[7];
    const float* Wk    = (const float*)d_in[8];
    const float* bk    = (const float*)d_in[9];
    const float* Wv    = (const float*)d_in[10];
    const float* bv    = (const float*)d_in[11];
    const float* gamma = (const float*)d_in[12];
    const float* Wb    = (const float*)d_in[13];
    const float* bn_bg = (const float*)d_in[14];
    const float* bn_bb = (const float*)d_in[15];
    float* out = (float*)d_out;

    float *conv, *xA, *xB, *rsum, *cs, *wf, *bf;
    __half *vth, *ohth, *qth, *kth, *aHh, *aWh, *wth;
    float2 *stats, *bnab;
    cudaGetSymbolAddress((void**)&conv, g_conv);
    cudaGetSymbolAddress((void**)&xA, g_xA);
    cudaGetSymbolAddress((void**)&xB, g_xB);
    cudaGetSymbolAddress((void**)&vth, g_vth);
    cudaGetSymbolAddress((void**)&ohth, g_ohth);
    cudaGetSymbolAddress((void**)&qth, g_qth);
    cudaGetSymbolAddress((void**)&kth, g_kth);
    cudaGetSymbolAddress((void**)&aHh, g_aHh);
    cudaGetSymbolAddress((void**)&aWh, g_aWh);
    cudaGetSymbolAddress((void**)&rsum, g_rsum);
    cudaGetSymbolAddress((void**)&wth, g_wth);
    cudaGetSymbolAddress((void**)&cs, g_cs);
    cudaGetSymbolAddress((void**)&stats, g_stats);
    cudaGetSymbolAddress((void**)&bnab, g_bnab);
    cudaGetSymbolAddress((void**)&wf, g_wf);
    cudaGetSymbolAddress((void**)&bf, g_bf);
    float* cs1 = cs;
    float* cs2 = cs + 64;

    // Idempotent, called unconditionally (no static guards — harness rule).
    cudaFuncSetAttribute(conv3x3_mma_kernel,
                         cudaFuncAttributeMaxDynamicSharedMemorySize, CONV_SMEM);
    cudaFuncSetAttribute(oH_kernel,
                         cudaFuncAttributeMaxDynamicSharedMemorySize, ATT_SMEM);
    cudaFuncSetAttribute(oW_combine_kernel,
                         cudaFuncAttributeMaxDynamicSharedMemorySize, ATT_SMEM);

    // Launch order keeps conv3x3 at capture index 3 (memsets are not kernel launches).
    conv1x1_c32_kernel<<<512, 256>>>(lf0, Wq, bq, qth);          // 0
    conv1x1_c32_kernel<<<512, 256>>>(lf1, Wk, bk, kth);          // 1
    wtrans_kernel<<<144, 256>>>(Wa, wth);                        // 2
    cudaMemsetAsync(cs, 0, 128 * sizeof(float));
    conv3x3_mma_kernel<<<dim3(4, 64, 4), 256, CONV_SMEM>>>(cost, wth, conv, cs1, cs2);  // 3

    // attention maps: exp(scores) + row sums (softmax fused; invariant across recurrence)
    cudaMemsetAsync(rsum, 0, NROWS * sizeof(float));
    eH_kernel<<<dim3(256, 4), 256>>>(qth, kth, aHh, rsum);
    eW_kernel<<<dim3(4, 128, 4), 256>>>(qth, kth, aWh, rsum);

    // BN stats for stage A (affine + folded v-conv weights; no bn_apply materialization)
    bn_finalize_kernel<<<1, 64>>>(cs1, cs2, bn_ag, bn_ab, stats, bnab);
    wfold_kernel<<<1, 64>>>(Wv, bv, bnab, wf, bf);

    // Stage C iteration 1: consumers read raw conv with BN fused in
    conv1x1_d64_kernel<<<512, 256>>>(conv, wf, bf, vth);
    oH_kernel<<<dim3(256, 4), 128, ATT_SMEM>>>(vth, aHh, rsum, ohth);
    oW_combine_kernel<<<dim3(2, 128, 4), 128, ATT_SMEM>>>(vth, aWh, ohth, conv, rsum,
                                                          bnab, 1, gamma, xB);
    // Stage C iteration 2: input xB already materialized
    conv1x1_d64_kernel<<<512, 256>>>(xB, Wv, bv, vth);
    oH_kernel<<<dim3(256, 4), 128, ATT_SMEM>>>(vth, aHh, rsum, ohth);
    oW_combine_kernel<<<dim3(2, 128, 4), 128, ATT_SMEM>>>(vth, aWh, ohth, xB, rsum,
                                                          bnab, 0, gamma, xA);

    // Stage D: conv3x3(xA, Wb) + BN -> out
    wtrans_kernel<<<144, 256>>>(Wb, wth);
    cudaMemsetAsync(cs, 0, 128 * sizeof(float));
    conv3x3_mma_kernel<<<dim3(4, 64, 4), 256, CONV_SMEM>>>(xA, wth, conv, cs1, cs2);
    bn_finalize_kernel<<<1, 64>>>(cs1, cs2, bn_bg, bn_bb, stats, bnab);
    bn_apply_kernel<<<8192, 256>>>(conv, stats, bn_bg, bn_bb, out);
}

// round 15
// speedup vs baseline: 1.0094x; 1.0094x over previous
#include <cuda_runtime.h>
#include <cuda_fp16.h>
#include <cstdint>
#include <cstddef>

#define BB 4
#define CC 32
#define DD 64
#define HH 128
#define WW 256
#define HW_ (HH*WW)          // 32768
#define BDHW_ (BB*DD*HW_)    // 8388608
#define BCHW_ (BB*CC*HW_)    // 4194304
#define NROWS (BB*HH*WW)     // 131072

// ---------------- scratch (static device globals; no allocation) ----------------
__device__ float g_conv[BDHW_];
__device__ float g_xA[BDHW_];
__device__ float g_xB[BDHW_];
__device__ __half g_vth[BDHW_];      // v fp16, [b][h][w][d]
__device__ __half g_ohth[BDHW_];     // oH fp16 (normalized), [b][h][w][d]
__device__ __half g_qth[BCHW_];      // q fp16, [b][h][w][c]
__device__ __half g_kth[BCHW_];      // k fp16, [b][h][w][c]
__device__ __half g_aHh[BB*HH*WW*HH];  // fp16 exp(scores) (H part)
__device__ __half g_aWh[BB*HH*WW*WW];  // fp16 exp(scores) (W part)
__device__ float g_rsum[NROWS];      // per-row softmax denominators
__device__ __half g_wth[9*64*64];    // fp16 conv weights [t][d][c]
__device__ float g_cs[128];          // channel sums [0:64] and sumsq [64:128]
__device__ float2 g_stats[64];       // (mean, inv)
__device__ float2 g_bnab[64];        // (sa, sb): BN as affine
__device__ float g_wf[64*64];        // BN-folded 1x1 v-conv weights
__device__ float g_bf[64];           // BN-folded bias

// ---------------- weight transform ----------------
__global__ void wtrans_kernel(const float* __restrict__ W, __half* __restrict__ wth) {
    const int i = blockIdx.x * 256 + threadIdx.x;
    if (i >= 9 * 64 * 64) return;
    const int t = i >> 12;
    const int d = (i >> 6) & 63;
    const int c = i & 63;
    wth[i] = __float2half(W[((d * 64 + c) * 9) + t]);
}

// ---------------- mma / ldmatrix helpers ----------------
__device__ __forceinline__ void mma_f16(float* c, uint32_t a0, uint32_t a1, uint32_t a2, uint32_t a3,
                                        uint32_t b0, uint32_t b1) {
    asm volatile("mma.sync.aligned.m16n8k16.row.col.f32.f16.f16.f32 "
                 "{%0,%1,%2,%3}, {%4,%5,%6,%7}, {%8,%9}, {%0,%1,%2,%3};"
                 : "+f"(c[0]), "+f"(c[1]), "+f"(c[2]), "+f"(c[3])
                 : "r"(a0), "r"(a1), "r"(a2), "r"(a3), "r"(b0), "r"(b1));
}

__device__ __forceinline__ uint32_t cvta_smem(const void* p) {
    return (uint32_t)__cvta_generic_to_shared(p);
}

__device__ __forceinline__ void ldsm_x4(uint32_t& r0, uint32_t& r1, uint32_t& r2, uint32_t& r3,
                                        uint32_t addr) {
    asm volatile("ldmatrix.sync.aligned.m8n8.x4.shared.b16 {%0,%1,%2,%3}, [%4];"
                 : "=r"(r0), "=r"(r1), "=r"(r2), "=r"(r3) : "r"(addr));
}

__device__ __forceinline__ void ldsm_x4_trans(uint32_t& r0, uint32_t& r1, uint32_t& r2, uint32_t& r3,
                                              uint32_t addr) {
    asm volatile("ldmatrix.sync.aligned.m8n8.x4.trans.shared.b16 {%0,%1,%2,%3}, [%4];"
                 : "=r"(r0), "=r"(r1), "=r"(r2), "=r"(r3) : "r"(addr));
}

// ---------------- fast exp ----------------
__device__ __forceinline__ float fexp(float x) {
    x = fmaxf(x, -80.f);
    const float y = x * 1.44269504f;
    const int e = __float2int_rn(y);
    const float f = y - (float)e;
    float p = 0.00133335581f;
    p = fmaf(p, f, 0.00961812910f);
    p = fmaf(p, f, 0.0555041086f);
    p = fmaf(p, f, 0.240226507f);
    p = fmaf(p, f, 0.693147182f);
    p = fmaf(p, f, 1.0f);
    return p * __int_as_float((e + 127) << 23);
}

// ---------------- conv3x3: fp16 mma + ldmatrix (round-13 mainloop) + BN-stat epilogue ----------------
#define CXS_STRIDE 72
#define CXS_HALVES (4*66*72)    // 19008
#define CWS_HALVES (64*72)      // 4608
#define CONV_SMEM ((CXS_HALVES + CWS_HALVES) * 2)   // 47232 bytes

__global__ __launch_bounds__(256)
void conv3x3_mma_kernel(const float* __restrict__ x, const __half* __restrict__ wth,
                        float* __restrict__ y, float* __restrict__ cs1, float* __restrict__ cs2) {
    extern __shared__ __half shc[];
    __half* xs = shc;                  // [(r*66+col)][72]
    __half* ws = shc + CXS_HALVES;     // [d][72]

    const int w0 = blockIdx.x * 64;
    const int h0 = blockIdx.y * 2;
    const int b  = blockIdx.z;
    const int tid = threadIdx.x;
    const int lane = tid & 31;
    const int warp = tid >> 5;
    const int hsel = warp >> 2;
    const int d0 = (warp & 3) * 16;
    const int g8 = lane >> 2;
    const int t2 = (lane & 3) * 2;

    for (int i = tid; i < 64 * 4 * 66; i += 256) {
        const int c = i / 264;
        const int rem = i - c * 264;
        const int r = rem / 66;
        const int col = rem - r * 66;
        const int gh = h0 + r - 1;
        const int gw = w0 + col - 1;
        float v = 0.f;
        if (gh >= 0 && gh < HH && gw >= 0 && gw < WW)
            v = x[((size_t)(b * 64 + c)) * HW_ + gh * WW + gw];
        xs[(r * 66 + col) * CXS_STRIDE + c] = __float2half(v);
    }

    float acc[8][4];
#pragma unroll
    for (int j = 0; j < 8; ++j)
#pragma unroll
        for (int k = 0; k < 4; ++k) acc[j][k] = 0.f;

    const uint32_t ws_base = cvta_smem(ws);
    const uint32_t xs_base = cvta_smem(xs);
    const uint32_t a_off = ((uint32_t)((d0 + (lane & 15)) * CXS_STRIDE + ((lane >> 4) << 3))) * 2;
    const uint32_t b_off = ((uint32_t)((((lane >> 4) << 3) + (lane & 7)) * CXS_STRIDE
                                       + (((lane >> 3) & 1) << 3))) * 2;

    for (int t = 0; t < 9; ++t) {
        __syncthreads();
        const __half* wp = wth + t * 4096;
        for (int i = tid; i < 4096; i += 256)
            ws[(i >> 6) * CXS_STRIDE + (i & 63)] = wp[i];
        __syncthreads();

        const int dh = t / 3;
        const int dw = t - dh * 3;
        const int colrow = (hsel + dh) * 66 + dw;
        const uint32_t b_tap = xs_base + b_off + (uint32_t)(colrow * CXS_STRIDE) * 2;
#pragma unroll
        for (int kb = 0; kb < 64; kb += 16) {
            uint32_t a0, a1, a2, a3;
            ldsm_x4(a0, a1, a2, a3, ws_base + a_off + kb * 2);
#pragma unroll
            for (int jj = 0; jj < 4; ++jj) {
                uint32_t b0, b1, c0, c1;
                ldsm_x4(b0, b1, c0, c1, b_tap + (uint32_t)(jj * 16 * CXS_STRIDE + kb) * 2);
                mma_f16(acc[2 * jj],     a0, a1, a2, a3, b0, b1);
                mma_f16(acc[2 * jj + 1], a0, a1, a2, a3, c0, c1);
            }
        }
    }

    const int h = h0 + hsel;
    float s_lo = 0.f, q_lo = 0.f, s_hi = 0.f, q_hi = 0.f;
#pragma unroll
    for (int j = 0; j < 8; ++j) {
        const int w = w0 + j * 8 + t2;
        const size_t base = ((size_t)(b * 64 + d0 + g8)) * HW_ + (size_t)h * WW + w;
        *reinterpret_cast<float2*>(y + base) = make_float2(acc[j][0], acc[j][1]);
        *reinterpret_cast<float2*>(y + base + (size_t)8 * HW_) = make_float2(acc[j][2], acc[j][3]);
        s_lo += acc[j][0] + acc[j][1];
        q_lo += acc[j][0] * acc[j][0] + acc[j][1] * acc[j][1];
        s_hi += acc[j][2] + acc[j][3];
        q_hi += acc[j][2] * acc[j][2] + acc[j][3] * acc[j][3];
    }
    s_lo += __shfl_xor_sync(0xffffffffu, s_lo, 1); s_lo += __shfl_xor_sync(0xffffffffu, s_lo, 2);
    q_lo += __shfl_xor_sync(0xffffffffu, q_lo, 1); q_lo += __shfl_xor_sync(0xffffffffu, q_lo, 2);
    s_hi += __shfl_xor_sync(0xffffffffu, s_hi, 1); s_hi += __shfl_xor_sync(0xffffffffu, s_hi, 2);
    q_hi += __shfl_xor_sync(0xffffffffu, q_hi, 1); q_hi += __shfl_xor_sync(0xffffffffu, q_hi, 2);
    if ((lane & 3) == 0) {
        atomicAdd(cs1 + d0 + g8, s_lo);
        atomicAdd(cs2 + d0 + g8, q_lo);
        atomicAdd(cs1 + d0 + g8 + 8, s_hi);
        atomicAdd(cs2 + d0 + g8 + 8, q_hi);
    }
}

// ---------------- BN finalize: stats + affine ----------------
__global__ void bn_finalize_kernel(const float* __restrict__ cs1, const float* __restrict__ cs2,
                                   const float* __restrict__ gam, const float* __restrict__ bet,
                                   float2* __restrict__ stats, float2* __restrict__ bnab) {
    const int c = threadIdx.x;
    const float inv_n = 1.f / 131072.f;
    const float mean = cs1[c] * inv_n;
    const float var  = cs2[c] * inv_n - mean * mean;
    const float inv  = rsqrtf(var + 1e-5f);
    stats[c] = make_float2(mean, inv);
    const float sa = inv * gam[c];
    bnab[c] = make_float2(sa, bet[c] - mean * sa);
}

// ---------------- fold BN into 1x1 v-conv weights ----------------
__global__ void wfold_kernel(const float* __restrict__ Wv, const float* __restrict__ bv,
                             const float2* __restrict__ bnab,
                             float* __restrict__ wf, float* __restrict__ bf) {
    const int dout = threadIdx.x;   // 64 threads
    float bb = bv[dout];
    for (int c = 0; c < 64; ++c) {
        const float w = Wv[dout * 64 + c];
        const float2 ab = bnab[c];
        wf[dout * 64 + c] = w * ab.x;
        bb += w * ab.y;
    }
    bf[dout] = bb;
}

// ---------------- bn_apply (stage D only) ----------------
__global__ void bn_apply_kernel(const float* __restrict__ x, const float2* __restrict__ stats,
                                const float* __restrict__ gam, const float* __restrict__ bet,
                                float* __restrict__ y) {
    const int idx = blockIdx.x * 256 + threadIdx.x;
    const int e = idx * 4;
    const int c = (e / HW_) & 63;
    const float2 st = stats[c];
    const float g = gam[c], be = bet[c];
    float4 v = reinterpret_cast<const float4*>(x)[idx];
    v.x = (v.x - st.x) * st.y * g + be;
    v.y = (v.y - st.x) * st.y * g + be;
    v.z = (v.z - st.x) * st.y * g + be;
    v.w = (v.w - st.x) * st.y * g + be;
    reinterpret_cast<float4*>(y)[idx] = v;
}

// ---------------- 1x1 convs ----------------
__global__ void conv1x1_c32_kernel(const float* __restrict__ x, const float* __restrict__ wgt,
                                   const float* __restrict__ bias, __half* __restrict__ yt) {
    __shared__ float sw[32][33];
    __shared__ float sb[32];
    const int tid = threadIdx.x;
    for (int i = tid; i < 1024; i += 256) sw[i >> 5][i & 31] = wgt[i];
    if (tid < 32) sb[tid] = bias[tid];
    __syncthreads();
    const int pos = blockIdx.x * 256 + tid;
    const int b = pos >> 15, i = pos & 32767;
    float xin[32];
#pragma unroll
    for (int ci = 0; ci < 32; ++ci) xin[ci] = x[((size_t)(b * 32 + ci)) * HW_ + i];
    __half* out = yt + (size_t)pos * 32;
#pragma unroll
    for (int co = 0; co < 32; co += 4) {
        float4 a = make_float4(sb[co], sb[co + 1], sb[co + 2], sb[co + 3]);
#pragma unroll
        for (int ci = 0; ci < 32; ++ci) {
            const float xv = xin[ci];
            a.x += sw[co][ci] * xv; a.y += sw[co + 1][ci] * xv;
            a.z += sw[co + 2][ci] * xv; a.w += sw[co + 3][ci] * xv;
        }
        *reinterpret_cast<__half2*>(out + co)     = __floats2half2_rn(a.x, a.y);
        *reinterpret_cast<__half2*>(out + co + 2) = __floats2half2_rn(a.z, a.w);
    }
}

__global__ void conv1x1_d64_kernel(const float* __restrict__ x, const float* __restrict__ wgt,
                                   const float* __restrict__ bias, __half* __restrict__ vth) {
    __shared__ float sw[64][65];
    __shared__ float sb[64];
    const int tid = threadIdx.x;
    for (int i = tid; i < 4096; i += 256) sw[i >> 6][i & 63] = wgt[i];
    if (tid < 64) sb[tid] = bias[tid];
    __syncthreads();
    const int pos = blockIdx.x * 256 + tid;
    const int b = pos >> 15, i = pos & 32767;
    float xin[64];
#pragma unroll
    for (int ci = 0; ci < 64; ++ci) xin[ci] = x[((size_t)(b * 64 + ci)) * HW_ + i];
    __half* out = vth + (size_t)pos * 64;
#pragma unroll
    for (int co = 0; co < 64; co += 4) {
        float4 a = make_float4(sb[co], sb[co + 1], sb[co + 2], sb[co + 3]);
#pragma unroll
        for (int ci = 0; ci < 64; ++ci) {
            const float xv = xin[ci];
            a.x += sw[co][ci] * xv; a.y += sw[co + 1][ci] * xv;
            a.z += sw[co + 2][ci] * xv; a.w += sw[co + 3][ci] * xv;
        }
        *reinterpret_cast<__half2*>(out + co)     = __floats2half2_rn(a.x, a.y);
        *reinterpret_cast<__half2*>(out + co + 2) = __floats2half2_rn(a.z, a.w);
    }
}

// ---------------- eH via HMMA + fused exp + row-sum ----------------
#define ES_STRIDE 40

__global__ __launch_bounds__(256)
void eH_kernel(const __half* __restrict__ qth, const __half* __restrict__ kth,
               __half* __restrict__ aHh, float* __restrict__ rsum) {
    __shared__ __half Qs[128 * ES_STRIDE];
    __shared__ __half Ks[128 * ES_STRIDE];
    const int w = blockIdx.x, b = blockIdx.y;
    const int tid = threadIdx.x;
    const int lane = tid & 31, warp = tid >> 5;
    const int g8 = lane >> 2, t2 = (lane & 3) * 2;

    for (int i = tid; i < 512; i += 256) {
        const int row = i >> 2, seg = (i & 3) * 8;
        const size_t gidx = (((size_t)b * HH + row) * WW + w) * 32 + seg;
        *reinterpret_cast<uint4*>(Qs + row * ES_STRIDE + seg) =
            *reinterpret_cast<const uint4*>(qth + gidx);
        *reinterpret_cast<uint4*>(Ks + row * ES_STRIDE + seg) =
            *reinterpret_cast<const uint4*>(kth + gidx);
    }
    __syncthreads();

    float acc[16][4];
#pragma unroll
    for (int ni = 0; ni < 16; ++ni)
#pragma unroll
        for (int k = 0; k < 4; ++k) acc[ni][k] = 0.f;

    const int h0 = warp * 16;
#pragma unroll
    for (int kb = 0; kb < 32; kb += 16) {
        const __half* ap = Qs + (h0 + g8) * ES_STRIDE + kb + t2;
        const uint32_t a0 = *reinterpret_cast<const uint32_t*>(ap);
        const uint32_t a1 = *reinterpret_cast<const uint32_t*>(ap + 8 * ES_STRIDE);
        const uint32_t a2 = *reinterpret_cast<const uint32_t*>(ap + 8);
        const uint32_t a3 = *reinterpret_cast<const uint32_t*>(ap + 8 * ES_STRIDE + 8);
#pragma unroll
        for (int ni = 0; ni < 16; ++ni) {
            const __half* bp = Ks + (ni * 8 + g8) * ES_STRIDE + kb + t2;
            const uint32_t b0 = *reinterpret_cast<const uint32_t*>(bp);
            const uint32_t b1 = *reinterpret_cast<const uint32_t*>(bp + 8);
            mma_f16(acc[ni], a0, a1, a2, a3, b0, b1);
        }
    }

    const int h1 = h0 + g8, h2 = h1 + 8;
    float s1 = 0.f, s2 = 0.f;
#pragma unroll
    for (int ni = 0; ni < 16; ++ni) {
        const int g = ni * 8 + t2;
        const float e0 = (h1 == g)     ? 0.f : fexp(acc[ni][0]);
        const float e1 = (h1 == g + 1) ? 0.f : fexp(acc[ni][1]);
        const float e2 = (h2 == g)     ? 0.f : fexp(acc[ni][2]);
        const float e3 = (h2 == g + 1) ? 0.f : fexp(acc[ni][3]);
        s1 += e0 + e1;
        s2 += e2 + e3;
        *reinterpret_cast<__half2*>(aHh + (((size_t)b * HH + h1) * WW + w) * 128 + g) =
            __floats2half2_rn(e0, e1);
        *reinterpret_cast<__half2*>(aHh + (((size_t)b * HH + h2) * WW + w) * 128 + g) =
            __floats2half2_rn(e2, e3);
    }
    s1 += __shfl_xor_sync(0xffffffffu, s1, 1);
    s1 += __shfl_xor_sync(0xffffffffu, s1, 2);
    s2 += __shfl_xor_sync(0xffffffffu, s2, 1);
    s2 += __shfl_xor_sync(0xffffffffu, s2, 2);
    if ((lane & 3) == 0) {
        atomicAdd(rsum + ((size_t)b * HH + h1) * WW + w, s1);
        atomicAdd(rsum + ((size_t)b * HH + h2) * WW + w, s2);
    }
}

// ---------------- eW via HMMA + fused exp + row-sum ----------------
__global__ __launch_bounds__(256)
void eW_kernel(const __half* __restrict__ qth, const __half* __restrict__ kth,
               __half* __restrict__ aWh, float* __restrict__ rsum) {
    __shared__ __half Qs[256 * ES_STRIDE];
    __shared__ __half Ks[64 * ES_STRIDE];
    const int gc = blockIdx.x * 64;
    const int h = blockIdx.y, b = blockIdx.z;
    const int tid = threadIdx.x;
    const int lane = tid & 31, warp = tid >> 5;
    const int g8 = lane >> 2, t2 = (lane & 3) * 2;

    const __half* qbase = qth + (((size_t)b * HH + h) * WW) * 32;
    for (int i = tid; i < 1024; i += 256) {
        const int row = i >> 2, seg = (i & 3) * 8;
        *reinterpret_cast<uint4*>(Qs + row * ES_STRIDE + seg) =
            *reinterpret_cast<const uint4*>(qbase + row * 32 + seg);
    }
    const __half* kbase = kth + (((size_t)b * HH + h) * WW + gc) * 32;
    {
        const int i = tid;
        const int row = i >> 2, seg = (i & 3) * 8;
        *reinterpret_cast<uint4*>(Ks + row * ES_STRIDE + seg) =
            *reinterpret_cast<const uint4*>(kbase + row * 32 + seg);
    }
    __syncthreads();

    float acc[2][8][4];
#pragma unroll
    for (int mi = 0; mi < 2; ++mi)
#pragma unroll
        for (int ni = 0; ni < 8; ++ni)
#pragma unroll
            for (int k = 0; k < 4; ++k) acc[mi][ni][k] = 0.f;

    const int w0 = warp * 32;
#pragma unroll
    for (int kb = 0; kb < 32; kb += 16) {
        uint32_t a[2][4];
#pragma unroll
        for (int mi = 0; mi < 2; ++mi) {
            const __half* ap = Qs + (w0 + mi * 16 + g8) * ES_STRIDE + kb + t2;
            a[mi][0] = *reinterpret_cast<const uint32_t*>(ap);
            a[mi][1] = *reinterpret_cast<const uint32_t*>(ap + 8 * ES_STRIDE);
            a[mi][2] = *reinterpret_cast<const uint32_t*>(ap + 8);
            a[mi][3] = *reinterpret_cast<const uint32_t*>(ap + 8 * ES_STRIDE + 8);
        }
#pragma unroll
        for (int ni = 0; ni < 8; ++ni) {
            const __half* bp = Ks + (ni * 8 + g8) * ES_STRIDE + kb + t2;
            const uint32_t b0 = *reinterpret_cast<const uint32_t*>(bp);
            const uint32_t b1 = *reinterpret_cast<const uint32_t*>(bp + 8);
            mma_f16(acc[0][ni], a[0][0], a[0][1], a[0][2], a[0][3], b0, b1);
            mma_f16(acc[1][ni], a[1][0], a[1][1], a[1][2], a[1][3], b0, b1);
        }
    }

#pragma unroll
    for (int mi = 0; mi < 2; ++mi) {
        const int w1 = w0 + mi * 16 + g8, w2 = w1 + 8;
        float s1 = 0.f, s2 = 0.f;
#pragma unroll
        for (int ni = 0; ni < 8; ++ni) {
            const int g = gc + ni * 8 + t2;
            const float e0 = fexp(acc[mi][ni][0]);
            const float e1 = fexp(acc[mi][ni][1]);
            const float e2 = fexp(acc[mi][ni][2]);
            const float e3 = fexp(acc[mi][ni][3]);
            s1 += e0 + e1;
            s2 += e2 + e3;
            *reinterpret_cast<__half2*>(aWh + (((size_t)b * HH + h) * WW + w1) * 256 + g) =
                __floats2half2_rn(e0, e1);
            *reinterpret_cast<__half2*>(aWh + (((size_t)b * HH + h) * WW + w2) * 256 + g) =
                __floats2half2_rn(e2, e3);
        }
        s1 += __shfl_xor_sync(0xffffffffu, s1, 1);
        s1 += __shfl_xor_sync(0xffffffffu, s1, 2);
        s2 += __shfl_xor_sync(0xffffffffu, s2, 1);
        s2 += __shfl_xor_sync(0xffffffffu, s2, 2);
        if ((lane & 3) == 0) {
            atomicAdd(rsum + ((size_t)b * HH + h) * WW + w1, s1);
            atomicAdd(rsum + ((size_t)b * HH + h) * WW + w2, s2);
        }
    }
}

// ---------------- oH via HMMA + ldmatrix + normalization ----------------
#define ATT_SSTRIDE 136
#define VS2_STRIDE 72
#define ATT_SMEM ((128*ATT_SSTRIDE + 128*VS2_STRIDE) * 2)   // 53248 bytes

__global__ void oH_kernel(const __half* __restrict__ vth, const __half* __restrict__ aHh,
                          const float* __restrict__ rsum, __half* __restrict__ ohth) {
    extern __shared__ __half sh[];
    __half* As = sh;                       // [128 h][136] g-contiguous
    __half* Vs = sh + 128 * ATT_SSTRIDE;   // [128 g][72] d-contiguous
    const int w = blockIdx.x, b = blockIdx.y;
    const int tid = threadIdx.x;
    const int lane = tid & 31, warp = tid >> 5;
    const int g8 = lane >> 2, t2 = (lane & 3) * 2;

    for (int i = tid; i < 2048; i += 128) {
        const int row = i >> 4, ch = (i & 15) * 8;
        *reinterpret_cast<uint4*>(As + row * ATT_SSTRIDE + ch) =
            *reinterpret_cast<const uint4*>(aHh + (((size_t)b * HH + row) * WW + w) * 128 + ch);
    }
    for (int i = tid; i < 1024; i += 128) {
        const int g = i >> 3, dc = (i & 7) * 8;
        *reinterpret_cast<uint4*>(Vs + g * VS2_STRIDE + dc) =
            *reinterpret_cast<const uint4*>(vth + (((size_t)b * HH + g) * WW + w) * 64 + dc);
    }
    __syncthreads();

    float acc[2][8][4];
#pragma unroll
    for (int mi = 0; mi < 2; ++mi)
#pragma unroll
        for (int ni = 0; ni < 8; ++ni)
#pragma unroll
            for (int k = 0; k < 4; ++k) acc[mi][ni][k] = 0.f;

    const uint32_t as_base = cvta_smem(As);
    const uint32_t vs_base = cvta_smem(Vs);
    const uint32_t a_off = ((uint32_t)((lane & 15) * ATT_SSTRIDE + ((lane >> 4) << 3))) * 2;
    const uint32_t b_off = ((uint32_t)((lane & 15) * VS2_STRIDE + ((lane >> 4) << 3))) * 2;

    const int h0 = warp * 32;
#pragma unroll
    for (int kb = 0; kb < 128; kb += 16) {
        uint32_t a[2][4];
#pragma unroll
        for (int mi = 0; mi < 2; ++mi)
            ldsm_x4(a[mi][0], a[mi][1], a[mi][2], a[mi][3],
                    as_base + a_off + (uint32_t)((h0 + mi * 16) * ATT_SSTRIDE + kb) * 2);
#pragma unroll
        for (int np = 0; np < 4; ++np) {
            uint32_t b0, b1, c0, c1;
            ldsm_x4_trans(b0, b1, c0, c1,
                          vs_base + b_off + (uint32_t)(kb * VS2_STRIDE + np * 16) * 2);
            mma_f16(acc[0][2 * np],     a[0][0], a[0][1], a[0][2], a[0][3], b0, b1);
            mma_f16(acc[0][2 * np + 1], a[0][0], a[0][1], a[0][2], a[0][3], c0, c1);
            mma_f16(acc[1][2 * np],     a[1][0], a[1][1], a[1][2], a[1][3], b0, b1);
            mma_f16(acc[1][2 * np + 1], a[1][0], a[1][1], a[1][2], a[1][3], c0, c1);
        }
    }

#pragma unroll
    for (int mi = 0; mi < 2; ++mi) {
        const int h = h0 + mi * 16 + g8;
        const float inv1 = 1.f / rsum[((size_t)b * HH + h) * WW + w];
        const float inv2 = 1.f / rsum[((size_t)b * HH + h + 8) * WW + w];
#pragma unroll
        for (int ni = 0; ni < 8; ++ni) {
            const int d = ni * 8 + t2;
            *reinterpret_cast<__half2*>(ohth + (((size_t)b * HH + h) * WW + w) * 64 + d) =
                __floats2half2_rn(acc[mi][ni][0] * inv1, acc[mi][ni][1] * inv1);
            *reinterpret_cast<__half2*>(ohth + (((size_t)b * HH + h + 8) * WW + w) * 64 + d) =
                __floats2half2_rn(acc[mi][ni][2] * inv2, acc[mi][ni][3] * inv2);
        }
    }
}

// ---------------- oW via HMMA + ldmatrix + normalization + combine (+opt residual BN) ----------------
__global__ void oW_combine_kernel(const __half* __restrict__ vth, const __half* __restrict__ aWh,
                                  const __half* __restrict__ ohth, const float* __restrict__ x,
                                  const float* __restrict__ rsum, const float2* __restrict__ bnab,
                                  const int apply_bn,
                                  const float* __restrict__ gamma, float* __restrict__ xout) {
    extern __shared__ __half sh[];
    __half* As = sh;                       // [128 w][136]
    __half* Vs = sh + 128 * ATT_SSTRIDE;   // [128 g][72]
    const int wb = blockIdx.x * 128;
    const int h = blockIdx.y, b = blockIdx.z;
    const int tid = threadIdx.x;
    const int lane = tid & 31, warp = tid >> 5;
    const int g8 = lane >> 2, t2 = (lane & 3) * 2;

    float acc[2][8][4];
#pragma unroll
    for (int mi = 0; mi < 2; ++mi)
#pragma unroll
        for (int ni = 0; ni < 8; ++ni)
#pragma unroll
            for (int k = 0; k < 4; ++k) acc[mi][ni][k] = 0.f;

    const uint32_t as_base = cvta_smem(As);
    const uint32_t vs_base = cvta_smem(Vs);
    const uint32_t a_off = ((uint32_t)((lane & 15) * ATT_SSTRIDE + ((lane >> 4) << 3))) * 2;
    const uint32_t b_off = ((uint32_t)((lane & 15) * VS2_STRIDE + ((lane >> 4) << 3))) * 2;

    const int w0 = warp * 32;
    for (int gc = 0; gc < 256; gc += 128) {
        __syncthreads();
        for (int i = tid; i < 2048; i += 128) {
            const int row = i >> 4, ch = (i & 15) * 8;
            *reinterpret_cast<uint4*>(As + row * ATT_SSTRIDE + ch) =
                *reinterpret_cast<const uint4*>(
                    aWh + (((size_t)b * HH + h) * WW + wb + row) * 256 + gc + ch);
        }
        for (int i = tid; i < 1024; i += 128) {
            const int g = i >> 3, dc = (i & 7) * 8;
            *reinterpret_cast<uint4*>(Vs + g * VS2_STRIDE + dc) =
                *reinterpret_cast<const uint4*>(
                    vth + (((size_t)b * HH + h) * WW + gc + g) * 64 + dc);
        }
        __syncthreads();

#pragma unroll
        for (int kb = 0; kb < 128; kb += 16) {
            uint32_t a[2][4];
#pragma unroll
            for (int mi = 0; mi < 2; ++mi)
                ldsm_x4(a[mi][0], a[mi][1], a[mi][2], a[mi][3],
                        as_base + a_off + (uint32_t)((w0 + mi * 16) * ATT_SSTRIDE + kb) * 2);
#pragma unroll
            for (int np = 0; np < 4; ++np) {
                uint32_t b0, b1, c0, c1;
                ldsm_x4_trans(b0, b1, c0, c1,
                              vs_base + b_off + (uint32_t)(kb * VS2_STRIDE + np * 16) * 2);
                mma_f16(acc[0][2 * np],     a[0][0], a[0][1], a[0][2], a[0][3], b0, b1);
                mma_f16(acc[0][2 * np + 1], a[0][0], a[0][1], a[0][2], a[0][3], c0, c1);
                mma_f16(acc[1][2 * np],     a[1][0], a[1][1], a[1][2], a[1][3], b0, b1);
                mma_f16(acc[1][2 * np + 1], a[1][0], a[1][1], a[1][2], a[1][3], c0, c1);
            }
        }
    }

    const float gam = *gamma;
#pragma unroll
    for (int mi = 0; mi < 2; ++mi) {
#pragma unroll
        for (int half = 0; half < 2; ++half) {
            const int w = wb + w0 + mi * 16 + g8 + half * 8;
            const float inv = 1.f / rsum[((size_t)b * HH + h) * WW + w];
#pragma unroll
            for (int ni = 0; ni < 8; ++ni) {
                const int d = ni * 8 + t2;
                float sa0 = 1.f, sb0 = 0.f, sa1 = 1.f, sb1 = 0.f;
                if (apply_bn) {
                    const float2 p0 = bnab[d];
                    const float2 p1 = bnab[d + 1];
                    sa0 = p0.x; sb0 = p0.y; sa1 = p1.x; sb1 = p1.y;
                }
                const float cA = acc[mi][ni][half * 2] * inv;
                const float cB = acc[mi][ni][half * 2 + 1] * inv;
                const float2 ohf = __half22float2(*reinterpret_cast<const __half2*>(
                    ohth + (((size_t)b * HH + h) * WW + w) * 64 + d));
                const size_t x0 = ((size_t)(b * 64 + d)) * HW_ + (size_t)h * WW + w;
                const size_t x1 = ((size_t)(b * 64 + d + 1)) * HW_ + (size_t)h * WW + w;
                xout[x0] = gam * (cA + ohf.x) + (sa0 * x[x0] + sb0);
                xout[x1] = gam * (cB + ohf.y) + (sa1 * x[x1] + sb1);
            }
        }
    }
}

// ---------------- host ----------------
extern "C" void kernel_launch(void* const* d_in, const int* in_sizes, int n_in,
                              void* d_out, int out_size) {
    const float* cost  = (const float*)d_in[0];
    const float* lf0   = (const float*)d_in[1];
    const float* lf1   = (const float*)d_in[2];
    const float* Wa    = (const float*)d_in[3];
    const float* bn_ag = (const float*)d_in[4];
    const float* bn_ab = (const float*)d_in[5];
    const float* Wq    = (const float*)d_in[6];
    const float* bq    = (const float*)d_in[7];
    const float* Wk    = (const float*)d_in[8];
    const float* bk    = (const float*)d_in[9];
    const float* Wv    = (const float*)d_in[10];
    const float* bv    = (const float*)d_in[11];
    const float* gamma = (const float*)d_in[12];
    const float* Wb    = (const float*)d_in[13];
    const float* bn_bg = (const float*)d_in[14];
    const float* bn_bb = (const float*)d_in[15];
    float* out = (float*)d_out;

    float *conv, *xA, *xB, *rsum, *cs, *wf, *bf;
    __half *vth, *ohth, *qth, *kth, *aHh, *aWh, *wth;
    float2 *stats, *bnab;
    cudaGetSymbolAddress((void**)&conv, g_conv);
    cudaGetSymbolAddress((void**)&xA, g_xA);
    cudaGetSymbolAddress((void**)&xB, g_xB);
    cudaGetSymbolAddress((void**)&vth, g_vth);
    cudaGetSymbolAddress((void**)&ohth, g_ohth);
    cudaGetSymbolAddress((void**)&qth, g_qth);
    cudaGetSymbolAddress((void**)&kth, g_kth);
    cudaGetSymbolAddress((void**)&aHh, g_aHh);
    cudaGetSymbolAddress((void**)&aWh, g_aWh);
    cudaGetSymbolAddress((void**)&rsum, g_rsum);
    cudaGetSymbolAddress((void**)&wth, g_wth);
    cudaGetSymbolAddress((void**)&cs, g_cs);
    cudaGetSymbolAddress((void**)&stats, g_stats);
    cudaGetSymbolAddress((void**)&bnab, g_bnab);
    cudaGetSymbolAddress((void**)&wf, g_wf);
    cudaGetSymbolAddress((void**)&bf, g_bf);
    float* cs1 = cs;
    float* cs2 = cs + 64;

    // Idempotent, called unconditionally (no static guards — harness rule).
    cudaFuncSetAttribute(conv3x3_mma_kernel,
                         cudaFuncAttributeMaxDynamicSharedMemorySize, CONV_SMEM);
    cudaFuncSetAttribute(oH_kernel,
                         cudaFuncAttributeMaxDynamicSharedMemorySize, ATT_SMEM);
    cudaFuncSetAttribute(oW_combine_kernel,
                         cudaFuncAttributeMaxDynamicSharedMemorySize, ATT_SMEM);

    // Launch order keeps conv3x3 at capture index 3 (memsets are not kernel launches).
    conv1x1_c32_kernel<<<512, 256>>>(lf0, Wq, bq, qth);          // 0
    conv1x1_c32_kernel<<<512, 256>>>(lf1, Wk, bk, kth);          // 1
    wtrans_kernel<<<144, 256>>>(Wa, wth);                        // 2
    cudaMemsetAsync(cs, 0, 128 * sizeof(float));
    conv3x3_mma_kernel<<<dim3(4, 64, 4), 256, CONV_SMEM>>>(cost, wth, conv, cs1, cs2);  // 3

    // attention maps: exp(scores) + row sums (softmax fused; invariant across recurrence)
    cudaMemsetAsync(rsum, 0, NROWS * sizeof(float));
    eH_kernel<<<dim3(256, 4), 256>>>(qth, kth, aHh, rsum);
    eW_kernel<<<dim3(4, 128, 4), 256>>>(qth, kth, aWh, rsum);

    // BN stats for stage A (affine + folded v-conv weights; no bn_apply materialization)
    bn_finalize_kernel<<<1, 64>>>(cs1, cs2, bn_ag, bn_ab, stats, bnab);
    wfold_kernel<<<1, 64>>>(Wv, bv, bnab, wf, bf);

    // Stage C iteration 1: consumers read raw conv with BN fused in
    conv1x1_d64_kernel<<<512, 256>>>(conv, wf, bf, vth);
    oH_kernel<<<dim3(256, 4), 128, ATT_SMEM>>>(vth, aHh, rsum, ohth);
    oW_combine_kernel<<<dim3(2, 128, 4), 128, ATT_SMEM>>>(vth, aWh, ohth, conv, rsum,
                                                          bnab, 1, gamma, xB);
    // Stage C iteration 2: input xB already materialized
    conv1x1_d64_kernel<<<512, 256>>>(xB, Wv, bv, vth);
    oH_kernel<<<dim3(256, 4), 128, ATT_SMEM>>>(vth, aHh, rsum, ohth);
    oW_combine_kernel<<<dim3(2, 128, 4), 128, ATT_SMEM>>>(vth, aWh, ohth, xB, rsum,
                                                          bnab, 0, gamma, xA);

    // Stage D: conv3x3(xA, Wb) + BN -> out
    wtrans_kernel<<<144, 256>>>(Wb, wth);
    cudaMemsetAsync(cs, 0, 128 * sizeof(float));
    conv3x3_mma_kernel<<<dim3(4, 64, 4), 256, CONV_SMEM>>>(xA, wth, conv, cs1, cs2);
    bn_finalize_kernel<<<1, 64>>>(cs1, cs2, bn_bg, bn_bb, stats, bnab);
    bn_apply_kernel<<<8192, 256>>>(conv, stats, bn_bg, bn_bb, out);
}